// round 7
// baseline (speedup 1.0000x reference)
#include <cuda_runtime.h>
#include <cuda_bf16.h>
#include <cstdint>

#define BB 4
#define LL 2048
#define DD 1024
#define HH 16
#define DKK 64
#define DFF 4096
#define MROWS (BB*LL)
#define ATTN_OFF ((size_t)MROWS*DD)
#define PAD 36
#define STG_WORDS (128*PAD)

// Scratch
__device__ float g_x[(size_t)MROWS*DD];
__device__ float g_q[(size_t)MROWS*DD];
__device__ float g_k[(size_t)MROWS*DD];
__device__ float g_v[(size_t)MROWS*DD];
__device__ float g_o[(size_t)MROWS*DD];
__device__ float g_y1[(size_t)MROWS*DD];
__device__ float g_z[(size_t)MROWS*DD];
__device__ float g_h[(size_t)MROWS*DFF];
__device__ float g_rowsum[(size_t)BB*HH*LL];

__device__ __forceinline__ uint32_t f2t(float x) {
    uint32_t u; asm("cvt.rna.tf32.f32 %0, %1;" : "=r"(u) : "f"(x)); return u;
}
__device__ __forceinline__ uint32_t f2tb(uint32_t b) {
    uint32_t u; asm("cvt.rna.tf32.f32 %0, %1;" : "=r"(u) : "f"(__uint_as_float(b))); return u;
}
__device__ __forceinline__ void mma8(float* c, const uint32_t* a, const uint32_t* b) {
    asm volatile(
        "mma.sync.aligned.m16n8k8.row.col.f32.tf32.tf32.f32 "
        "{%0,%1,%2,%3},{%4,%5,%6,%7},{%8,%9},{%0,%1,%2,%3};"
        : "+f"(c[0]), "+f"(c[1]), "+f"(c[2]), "+f"(c[3])
        : "r"(a[0]), "r"(a[1]), "r"(a[2]), "r"(a[3]), "r"(b[0]), "r"(b[1]));
}
#define CP16(dst_u32, src_ptr) \
    asm volatile("cp.async.cg.shared.global [%0], [%1], 16;\n" :: "r"(dst_u32), "l"(src_ptr))
#define CP_COMMIT() asm volatile("cp.async.commit_group;\n" ::: "memory")
#define CP_WAIT(n)  asm volatile("cp.async.wait_group %0;\n" :: "n"(n) : "memory")

// ---------------------------------------------------------------------------
// Zero rowsum
// ---------------------------------------------------------------------------
__global__ void zero_kernel(float* __restrict__ p, int n) {
    int i = blockIdx.x * 256 + threadIdx.x;
    if (i < n) p[i] = 0.f;
}

// ---------------------------------------------------------------------------
// LayerNorm
// ---------------------------------------------------------------------------
__global__ void __launch_bounds__(256) ln_kernel(const float* __restrict__ in,
                                                 const float* __restrict__ gamma,
                                                 const float* __restrict__ beta,
                                                 float* __restrict__ out) {
    int row = blockIdx.x;
    const float* x = in + (size_t)row * DD;
    float* y = out + (size_t)row * DD;
    int t = threadIdx.x;
    float v[4];
    float s = 0.f;
#pragma unroll
    for (int i = 0; i < 4; i++) { v[i] = x[t + 256 * i]; s += v[i]; }
    __shared__ float red[32];
#pragma unroll
    for (int o = 16; o; o >>= 1) s += __shfl_xor_sync(0xffffffffu, s, o);
    if ((t & 31) == 0) red[t >> 5] = s;
    __syncthreads();
    if (t < 32) {
        float z = (t < 8) ? red[t] : 0.f;
#pragma unroll
        for (int o = 4; o; o >>= 1) z += __shfl_xor_sync(0xffffffffu, z, o);
        if (t == 0) red[0] = z;
    }
    __syncthreads();
    float mu = red[0] * (1.f / DD);
    __syncthreads();
    float s2 = 0.f;
#pragma unroll
    for (int i = 0; i < 4; i++) { float d = v[i] - mu; s2 += d * d; }
#pragma unroll
    for (int o = 16; o; o >>= 1) s2 += __shfl_xor_sync(0xffffffffu, s2, o);
    if ((t & 31) == 0) red[t >> 5] = s2;
    __syncthreads();
    if (t < 32) {
        float z = (t < 8) ? red[t] : 0.f;
#pragma unroll
        for (int o = 4; o; o >>= 1) z += __shfl_xor_sync(0xffffffffu, z, o);
        if (t == 0) red[0] = z;
    }
    __syncthreads();
    float rstd = rsqrtf(red[0] * (1.f / DD) + 1e-6f);
#pragma unroll
    for (int i = 0; i < 4; i++) {
        int c = t + 256 * i;
        y[c] = (v[i] - mu) * rstd * gamma[c] + beta[c];
    }
}

// ---------------------------------------------------------------------------
// tf32 GEMM with cp.async 2-stage pipeline: C = A[M,K] @ B[N,K]^T
// Dynamic smem: [2][128*PAD] A raw fp32 + [2][128*PAD] B raw fp32.
// cvt to tf32 at fragment-load time (identical numerics).
// EPI: 0 none, 1 relu(acc+bias), 2 acc+bias+res, 3 acc+res
// ---------------------------------------------------------------------------
template <int EPI>
__global__ void __launch_bounds__(256, 2) gemm_tc(
    const float* __restrict__ A, int lda,
    const float* __restrict__ B, int ldb,
    float* __restrict__ C, int ldc, int K,
    const float* __restrict__ bias,
    const float* __restrict__ res, int ldres) {
    extern __shared__ uint32_t sh[];
    uint32_t* AsBase = sh;                    // 2 stages
    uint32_t* BsBase = sh + 2 * STG_WORDS;    // 2 stages
    int bm = blockIdx.y * 128, bn = blockIdx.x * 128;
    int tid = threadIdx.x, lane = tid & 31, warp = tid >> 5;
    int wm = (warp & 3) * 32, wn = (warp >> 2) * 64;
    int lq = lane >> 2, lr = lane & 3;
    float acc[2][8][4];
#pragma unroll
    for (int mi = 0; mi < 2; mi++)
#pragma unroll
        for (int ni = 0; ni < 8; ni++)
#pragma unroll
            for (int j = 0; j < 4; j++) acc[mi][ni][j] = 0.f;

    int myrow = tid >> 3;           // 0..31 (+32*i)
    int myc4 = (tid & 7) << 2;      // 0,4,..,28

    auto issue = [&](int k0, int buf) {
        uint32_t* Asb = AsBase + buf * STG_WORDS;
        uint32_t* Bsb = BsBase + buf * STG_WORDS;
#pragma unroll
        for (int i = 0; i < 4; i++) {
            int row = myrow + i * 32;
            const float* ga = A + (size_t)(bm + row) * lda + k0 + myc4;
            uint32_t sa = (uint32_t)__cvta_generic_to_shared(&Asb[row * PAD + myc4]);
            CP16(sa, ga);
            const float* gb = B + (size_t)(bn + row) * ldb + k0 + myc4;
            uint32_t sb = (uint32_t)__cvta_generic_to_shared(&Bsb[row * PAD + myc4]);
            CP16(sb, gb);
        }
        CP_COMMIT();
    };

    int nk = K >> 5;
    issue(0, 0);
    for (int ki = 0; ki < nk; ki++) {
        if (ki + 1 < nk) { issue((ki + 1) << 5, (ki + 1) & 1); CP_WAIT(1); }
        else { CP_WAIT(0); }
        __syncthreads();
        const uint32_t* As = AsBase + (ki & 1) * STG_WORDS;
        const uint32_t* Bs = BsBase + (ki & 1) * STG_WORDS;
#pragma unroll
        for (int ks = 0; ks < 4; ks++) {
            int kk = ks * 8;
            uint32_t af[2][4], bf[8][2];
#pragma unroll
            for (int mi = 0; mi < 2; mi++) {
                int r = wm + mi * 16 + lq;
                af[mi][0] = f2tb(As[r * PAD + kk + lr]);
                af[mi][1] = f2tb(As[(r + 8) * PAD + kk + lr]);
                af[mi][2] = f2tb(As[r * PAD + kk + lr + 4]);
                af[mi][3] = f2tb(As[(r + 8) * PAD + kk + lr + 4]);
            }
#pragma unroll
            for (int ni = 0; ni < 8; ni++) {
                int n = wn + ni * 8 + lq;
                bf[ni][0] = f2tb(Bs[n * PAD + kk + lr]);
                bf[ni][1] = f2tb(Bs[n * PAD + kk + lr + 4]);
            }
#pragma unroll
            for (int mi = 0; mi < 2; mi++)
#pragma unroll
                for (int ni = 0; ni < 8; ni++) mma8(acc[mi][ni], af[mi], bf[ni]);
        }
        __syncthreads();
    }
#pragma unroll
    for (int mi = 0; mi < 2; mi++) {
        int r0 = bm + wm + mi * 16 + lq;
#pragma unroll
        for (int ni = 0; ni < 8; ni++) {
            int col = bn + wn + ni * 8 + 2 * lr;
#pragma unroll
            for (int rr = 0; rr < 2; rr++) {
                int m = r0 + rr * 8;
                float v0 = acc[mi][ni][rr * 2 + 0];
                float v1 = acc[mi][ni][rr * 2 + 1];
                if (EPI == 1) { v0 = fmaxf(v0 + bias[col], 0.f); v1 = fmaxf(v1 + bias[col + 1], 0.f); }
                if (EPI == 2) {
                    v0 += bias[col] + res[(size_t)m * ldres + col];
                    v1 += bias[col + 1] + res[(size_t)m * ldres + col + 1];
                }
                if (EPI == 3) {
                    v0 += res[(size_t)m * ldres + col];
                    v1 += res[(size_t)m * ldres + col + 1];
                }
                *(float2*)(C + (size_t)m * ldc + col) = make_float2(v0, v1);
            }
        }
    }
}

// ---------------------------------------------------------------------------
// Scores: per (b,h) s = (Q K^T)/8 * prior, masked -> attn region (raw s).
// Also accumulates rowsum[z,m] += sum_cols exp(s) via shfl+atomicAdd.
// ---------------------------------------------------------------------------
__global__ void __launch_bounds__(256, 2) scores_tc(
    const float* __restrict__ q, const float* __restrict__ k,
    const float* __restrict__ prior, const int* __restrict__ mask,
    float* __restrict__ attn, float* __restrict__ rowsum) {
    int z = blockIdx.z;
    int b = z >> 4, h = z & 15;
    const float* A = q + (size_t)b * LL * DD + h * DKK;
    const float* B = k + (size_t)b * LL * DD + h * DKK;
    float* Cp = attn + (size_t)z * LL * LL;
    int bm = blockIdx.y * 128, bn = blockIdx.x * 128;
    __shared__ uint32_t As[128 * PAD];
    __shared__ uint32_t Bs[128 * PAD];
    int tid = threadIdx.x, lane = tid & 31, warp = tid >> 5;
    int wm = (warp & 3) * 32, wn = (warp >> 2) * 64;
    int lq = lane >> 2, lr = lane & 3;
    float acc[2][8][4];
#pragma unroll
    for (int mi = 0; mi < 2; mi++)
#pragma unroll
        for (int ni = 0; ni < 8; ni++)
#pragma unroll
            for (int j = 0; j < 4; j++) acc[mi][ni][j] = 0.f;

    for (int k0 = 0; k0 < DKK; k0 += 32) {
#pragma unroll
        for (int i = 0; i < 4; i++) {
            int idx = tid + i * 256;
            int row = idx >> 3, c4 = (idx & 7) << 2;
            float4 va = *(const float4*)(A + (size_t)(bm + row) * DD + k0 + c4);
            As[row * PAD + c4 + 0] = f2t(va.x); As[row * PAD + c4 + 1] = f2t(va.y);
            As[row * PAD + c4 + 2] = f2t(va.z); As[row * PAD + c4 + 3] = f2t(va.w);
            float4 vb = *(const float4*)(B + (size_t)(bn + row) * DD + k0 + c4);
            Bs[row * PAD + c4 + 0] = f2t(vb.x); Bs[row * PAD + c4 + 1] = f2t(vb.y);
            Bs[row * PAD + c4 + 2] = f2t(vb.z); Bs[row * PAD + c4 + 3] = f2t(vb.w);
        }
        __syncthreads();
#pragma unroll
        for (int ks = 0; ks < 4; ks++) {
            int kk = ks * 8;
            uint32_t af[2][4], bf[8][2];
#pragma unroll
            for (int mi = 0; mi < 2; mi++) {
                int r = wm + mi * 16 + lq;
                af[mi][0] = As[r * PAD + kk + lr];
                af[mi][1] = As[(r + 8) * PAD + kk + lr];
                af[mi][2] = As[r * PAD + kk + lr + 4];
                af[mi][3] = As[(r + 8) * PAD + kk + lr + 4];
            }
#pragma unroll
            for (int ni = 0; ni < 8; ni++) {
                int n = wn + ni * 8 + lq;
                bf[ni][0] = Bs[n * PAD + kk + lr];
                bf[ni][1] = Bs[n * PAD + kk + lr + 4];
            }
#pragma unroll
            for (int mi = 0; mi < 2; mi++)
#pragma unroll
                for (int ni = 0; ni < 8; ni++) mma8(acc[mi][ni], af[mi], bf[ni]);
        }
        __syncthreads();
    }
    float rsum[2][2] = {{0.f, 0.f}, {0.f, 0.f}};
#pragma unroll
    for (int mi = 0; mi < 2; mi++) {
        int r0 = bm + wm + mi * 16 + lq;
#pragma unroll
        for (int ni = 0; ni < 8; ni++) {
            int col = bn + wn + ni * 8 + 2 * lr;
            int m0 = mask[b * LL + col], m1 = mask[b * LL + col + 1];
#pragma unroll
            for (int rr = 0; rr < 2; rr++) {
                int m = r0 + rr * 8;
                const float* prow = prior + ((size_t)b * LL + m) * LL + col;
                float v0 = acc[mi][ni][rr * 2 + 0] * 0.125f * prow[0];
                float v1 = acc[mi][ni][rr * 2 + 1] * 0.125f * prow[1];
                if (m0 == 0) v0 = -1e9f;
                if (m1 == 0) v1 = -1e9f;
                rsum[mi][rr] += __expf(v0) + __expf(v1);
                *(float2*)(Cp + (size_t)m * LL + col) = make_float2(v0, v1);
            }
        }
    }
#pragma unroll
    for (int mi = 0; mi < 2; mi++)
#pragma unroll
        for (int rr = 0; rr < 2; rr++) {
            float s = rsum[mi][rr];
            s += __shfl_xor_sync(0xffffffffu, s, 1);
            s += __shfl_xor_sync(0xffffffffu, s, 2);
            if (lr == 0) {
                int m = bm + wm + mi * 16 + lq + rr * 8;
                atomicAdd(&rowsum[(size_t)z * LL + m], s);
            }
        }
}

// ---------------------------------------------------------------------------
// AV: reads raw s, applies p = exp(s)/rowsum, writes p (final attn output),
// and computes O = P @ V per (b,h). grid (1,16,64)
// ---------------------------------------------------------------------------
#define VPAD 68
__global__ void __launch_bounds__(256, 2) av_tc(float* __restrict__ attn,
                                                const float* __restrict__ v,
                                                const float* __restrict__ rowsum,
                                                float* __restrict__ o) {
    int z = blockIdx.z;
    int b = z >> 4, h = z & 15;
    float* A = attn + (size_t)z * LL * LL;
    const float* Vp = v + (size_t)b * LL * DD + h * DKK;
    float* Cp = o + (size_t)b * LL * DD + h * DKK;
    int bm = blockIdx.y * 128;
    __shared__ uint32_t As[128 * PAD];
    __shared__ uint32_t Bs[32 * VPAD];
    __shared__ float invl[128];
    int tid = threadIdx.x, lane = tid & 31, warp = tid >> 5;
    int wm = warp * 16;
    int lq = lane >> 2, lr = lane & 3;
    if (tid < 128) invl[tid] = 1.f / rowsum[(size_t)z * LL + bm + tid];
    __syncthreads();
    float acc[8][4];
#pragma unroll
    for (int ni = 0; ni < 8; ni++)
#pragma unroll
        for (int j = 0; j < 4; j++) acc[ni][j] = 0.f;

    for (int k0 = 0; k0 < LL; k0 += 32) {
#pragma unroll
        for (int i = 0; i < 4; i++) {
            int idx = tid + i * 256;
            int row = idx >> 3, c4 = (idx & 7) << 2;
            float* ga = A + (size_t)(bm + row) * LL + k0 + c4;
            float4 va = *(const float4*)ga;
            float il = invl[row];
            va.x = __expf(va.x) * il; va.y = __expf(va.y) * il;
            va.z = __expf(va.z) * il; va.w = __expf(va.w) * il;
            *(float4*)ga = va;   // final normalized attn output
            As[row * PAD + c4 + 0] = f2t(va.x); As[row * PAD + c4 + 1] = f2t(va.y);
            As[row * PAD + c4 + 2] = f2t(va.z); As[row * PAD + c4 + 3] = f2t(va.w);
        }
#pragma unroll
        for (int i = 0; i < 2; i++) {
            int idx = tid + i * 256;
            int krow = idx >> 4, c4 = (idx & 15) << 2;
            float4 vb = *(const float4*)(Vp + (size_t)(k0 + krow) * DD + c4);
            Bs[krow * VPAD + c4 + 0] = f2t(vb.x); Bs[krow * VPAD + c4 + 1] = f2t(vb.y);
            Bs[krow * VPAD + c4 + 2] = f2t(vb.z); Bs[krow * VPAD + c4 + 3] = f2t(vb.w);
        }
        __syncthreads();
#pragma unroll
        for (int ks = 0; ks < 4; ks++) {
            int kk = ks * 8;
            uint32_t af[4], bf[8][2];
            int r = wm + lq;
            af[0] = As[r * PAD + kk + lr];
            af[1] = As[(r + 8) * PAD + kk + lr];
            af[2] = As[r * PAD + kk + lr + 4];
            af[3] = As[(r + 8) * PAD + kk + lr + 4];
#pragma unroll
            for (int ni = 0; ni < 8; ni++) {
                int n = ni * 8 + lq;
                bf[ni][0] = Bs[(kk + lr) * VPAD + n];
                bf[ni][1] = Bs[(kk + lr + 4) * VPAD + n];
            }
#pragma unroll
            for (int ni = 0; ni < 8; ni++) mma8(acc[ni], af, bf[ni]);
        }
        __syncthreads();
    }
    int r0 = bm + wm + lq;
#pragma unroll
    for (int ni = 0; ni < 8; ni++) {
        int col = ni * 8 + 2 * lr;
#pragma unroll
        for (int rr = 0; rr < 2; rr++) {
            int m = r0 + rr * 8;
            *(float2*)(Cp + (size_t)m * DD + col) =
                make_float2(acc[ni][rr * 2 + 0], acc[ni][rr * 2 + 1]);
        }
    }
}

// ---------------------------------------------------------------------------
// Launch
// ---------------------------------------------------------------------------
extern "C" void kernel_launch(void* const* d_in, const int* in_sizes, int n_in,
                              void* d_out, int out_size) {
    const float* src    = (const float*)d_in[0];
    const int*   mask   = (const int*)d_in[1];
    const float* prior  = (const float*)d_in[2];
    const float* ln1_g  = (const float*)d_in[3];
    const float* ln1_b  = (const float*)d_in[4];
    const float* wq     = (const float*)d_in[5];
    const float* wk     = (const float*)d_in[6];
    const float* wv     = (const float*)d_in[7];
    const float* fc_w   = (const float*)d_in[8];
    const float* ln2_g  = (const float*)d_in[9];
    const float* ln2_b  = (const float*)d_in[10];
    const float* w1_w   = (const float*)d_in[11];
    const float* w1_b   = (const float*)d_in[12];
    const float* w2_w   = (const float*)d_in[13];
    const float* w2_b   = (const float*)d_in[14];

    float* out = (float*)d_out;
    float* y_out = out;
    float* attn_out = out + ATTN_OFF;

    float *x, *q, *k, *v, *o, *y1, *zz, *hh, *rs;
    cudaGetSymbolAddress((void**)&x,  g_x);
    cudaGetSymbolAddress((void**)&q,  g_q);
    cudaGetSymbolAddress((void**)&k,  g_k);
    cudaGetSymbolAddress((void**)&v,  g_v);
    cudaGetSymbolAddress((void**)&o,  g_o);
    cudaGetSymbolAddress((void**)&y1, g_y1);
    cudaGetSymbolAddress((void**)&zz, g_z);
    cudaGetSymbolAddress((void**)&hh, g_h);
    cudaGetSymbolAddress((void**)&rs, g_rowsum);

    const int GSMEM = 4 * 4 * STG_WORDS;  // 73728 bytes
    static bool attr_set = false;
    if (!attr_set) {
        cudaFuncSetAttribute(gemm_tc<0>, cudaFuncAttributeMaxDynamicSharedMemorySize, GSMEM);
        cudaFuncSetAttribute(gemm_tc<1>, cudaFuncAttributeMaxDynamicSharedMemorySize, GSMEM);
        cudaFuncSetAttribute(gemm_tc<2>, cudaFuncAttributeMaxDynamicSharedMemorySize, GSMEM);
        cudaFuncSetAttribute(gemm_tc<3>, cudaFuncAttributeMaxDynamicSharedMemorySize, GSMEM);
        attr_set = true;
    }

    zero_kernel<<<(BB * HH * LL + 255) / 256, 256>>>(rs, BB * HH * LL);
    ln_kernel<<<MROWS, 256>>>(src, ln1_g, ln1_b, x);

    dim3 gproj(DD / 128, MROWS / 128);
    gemm_tc<0><<<gproj, 256, GSMEM>>>(x, DD, wq, DD, q, DD, DD, nullptr, nullptr, 0);
    gemm_tc<0><<<gproj, 256, GSMEM>>>(x, DD, wk, DD, k, DD, DD, nullptr, nullptr, 0);
    gemm_tc<0><<<gproj, 256, GSMEM>>>(x, DD, wv, DD, v, DD, DD, nullptr, nullptr, 0);

    scores_tc<<<dim3(LL / 128, LL / 128, BB * HH), 256>>>(q, k, prior, mask, attn_out, rs);

    av_tc<<<dim3(1, LL / 128, BB * HH), 256>>>(attn_out, v, rs, o);

    gemm_tc<3><<<gproj, 256, GSMEM>>>(o, DD, fc_w, DD, y1, DD, DD, nullptr, src, DD);

    ln_kernel<<<MROWS, 256>>>(y1, ln2_g, ln2_b, zz);

    gemm_tc<1><<<dim3(DFF / 128, MROWS / 128), 256, GSMEM>>>(zz, DD, w1_w, DD, hh, DFF, DD, w1_b, nullptr, 0);

    gemm_tc<2><<<gproj, 256, GSMEM>>>(hh, DFF, w2_w, DFF, y_out, DD, DFF, w2_b, y1, DD);
}

// round 8
// speedup vs baseline: 1.1889x; 1.1889x over previous
#include <cuda_runtime.h>
#include <cuda_bf16.h>
#include <cstdint>

#define BB 4
#define LL 2048
#define DD 1024
#define HH 16
#define DKK 64
#define DFF 4096
#define MROWS (BB*LL)
#define ATTN_OFF ((size_t)MROWS*DD)
#define PAD 36
#define STG_WORDS (128*PAD)

// Scratch
__device__ float g_x[(size_t)MROWS*DD];
__device__ float g_q[(size_t)MROWS*DD];
__device__ float g_k[(size_t)MROWS*DD];
__device__ float g_v[(size_t)MROWS*DD];
__device__ float g_o[(size_t)MROWS*DD];
__device__ float g_y1[(size_t)MROWS*DD];
__device__ float g_z[(size_t)MROWS*DD];
__device__ float g_h[(size_t)MROWS*DFF];
// tf32-rounded weight copies
__device__ float g_wqt[(size_t)DD*DD];
__device__ float g_wkt[(size_t)DD*DD];
__device__ float g_wvt[(size_t)DD*DD];
__device__ float g_fct[(size_t)DD*DD];
__device__ float g_w1t[(size_t)DFF*DD];
__device__ float g_w2t[(size_t)DD*DFF];

__device__ __forceinline__ float tf32r(float x) {
    uint32_t u; asm("cvt.rna.tf32.f32 %0, %1;" : "=r"(u) : "f"(x));
    return __uint_as_float(u);
}
__device__ __forceinline__ uint32_t f2t(float x) {
    uint32_t u; asm("cvt.rna.tf32.f32 %0, %1;" : "=r"(u) : "f"(x)); return u;
}
__device__ __forceinline__ void mma8(float* c, const uint32_t* a, const uint32_t* b) {
    asm volatile(
        "mma.sync.aligned.m16n8k8.row.col.f32.tf32.tf32.f32 "
        "{%0,%1,%2,%3},{%4,%5,%6,%7},{%8,%9},{%0,%1,%2,%3};"
        : "+f"(c[0]), "+f"(c[1]), "+f"(c[2]), "+f"(c[3])
        : "r"(a[0]), "r"(a[1]), "r"(a[2]), "r"(a[3]), "r"(b[0]), "r"(b[1]));
}
#define CP16(dst_u32, src_ptr) \
    asm volatile("cp.async.cg.shared.global [%0], [%1], 16;\n" :: "r"(dst_u32), "l"(src_ptr))
#define CP_COMMIT() asm volatile("cp.async.commit_group;\n" ::: "memory")
#define CP_WAIT(n)  asm volatile("cp.async.wait_group %0;\n" :: "n"(n) : "memory")

// ---------------------------------------------------------------------------
// Weight pre-round: out[i] = tf32(in[i])
// ---------------------------------------------------------------------------
__global__ void __launch_bounds__(256) cvt_kernel(const float* __restrict__ in,
                                                  float* __restrict__ out, int n4) {
    int i = blockIdx.x * 256 + threadIdx.x;
    if (i < n4) {
        float4 v = ((const float4*)in)[i];
        v.x = tf32r(v.x); v.y = tf32r(v.y); v.z = tf32r(v.z); v.w = tf32r(v.w);
        ((float4*)out)[i] = v;
    }
}

// ---------------------------------------------------------------------------
// LayerNorm; output rounded to tf32 (only ever feeds GEMM A operands)
// ---------------------------------------------------------------------------
__global__ void __launch_bounds__(256) ln_kernel(const float* __restrict__ in,
                                                 const float* __restrict__ gamma,
                                                 const float* __restrict__ beta,
                                                 float* __restrict__ out) {
    int row = blockIdx.x;
    const float* x = in + (size_t)row * DD;
    float* y = out + (size_t)row * DD;
    int t = threadIdx.x;
    float v[4];
    float s = 0.f;
#pragma unroll
    for (int i = 0; i < 4; i++) { v[i] = x[t + 256 * i]; s += v[i]; }
    __shared__ float red[32];
#pragma unroll
    for (int o = 16; o; o >>= 1) s += __shfl_xor_sync(0xffffffffu, s, o);
    if ((t & 31) == 0) red[t >> 5] = s;
    __syncthreads();
    if (t < 32) {
        float z = (t < 8) ? red[t] : 0.f;
#pragma unroll
        for (int o = 4; o; o >>= 1) z += __shfl_xor_sync(0xffffffffu, z, o);
        if (t == 0) red[0] = z;
    }
    __syncthreads();
    float mu = red[0] * (1.f / DD);
    __syncthreads();
    float s2 = 0.f;
#pragma unroll
    for (int i = 0; i < 4; i++) { float d = v[i] - mu; s2 += d * d; }
#pragma unroll
    for (int o = 16; o; o >>= 1) s2 += __shfl_xor_sync(0xffffffffu, s2, o);
    if ((t & 31) == 0) red[t >> 5] = s2;
    __syncthreads();
    if (t < 32) {
        float z = (t < 8) ? red[t] : 0.f;
#pragma unroll
        for (int o = 4; o; o >>= 1) z += __shfl_xor_sync(0xffffffffu, z, o);
        if (t == 0) red[0] = z;
    }
    __syncthreads();
    float rstd = rsqrtf(red[0] * (1.f / DD) + 1e-6f);
#pragma unroll
    for (int i = 0; i < 4; i++) {
        int c = t + 256 * i;
        y[c] = tf32r((v[i] - mu) * rstd * gamma[c] + beta[c]);
    }
}

// ---------------------------------------------------------------------------
// tf32 GEMM, cp.async 2-stage, NO cvt anywhere (inputs pre-rounded).
// C = A[M,K] @ B[N,K]^T.  EPI: 0 none, 1 relu(acc+bias), 2 acc+bias+res, 3 acc+res
// RND: round stored C to tf32 (when C feeds a later GEMM).
// ---------------------------------------------------------------------------
template <int EPI, bool RND>
__global__ void __launch_bounds__(256, 2) gemm_tc(
    const float* __restrict__ A, int lda,
    const float* __restrict__ B, int ldb,
    float* __restrict__ C, int ldc, int K,
    const float* __restrict__ bias,
    const float* __restrict__ res, int ldres) {
    extern __shared__ uint32_t sh[];
    uint32_t* AsBase = sh;
    uint32_t* BsBase = sh + 2 * STG_WORDS;
    int bm = blockIdx.y * 128, bn = blockIdx.x * 128;
    int tid = threadIdx.x, lane = tid & 31, warp = tid >> 5;
    int wm = (warp & 3) * 32, wn = (warp >> 2) * 64;
    int lq = lane >> 2, lr = lane & 3;
    float acc[2][8][4];
#pragma unroll
    for (int mi = 0; mi < 2; mi++)
#pragma unroll
        for (int ni = 0; ni < 8; ni++)
#pragma unroll
            for (int j = 0; j < 4; j++) acc[mi][ni][j] = 0.f;

    int myrow = tid >> 3;
    int myc4 = (tid & 7) << 2;

    auto issue = [&](int k0, int buf) {
        uint32_t* Asb = AsBase + buf * STG_WORDS;
        uint32_t* Bsb = BsBase + buf * STG_WORDS;
#pragma unroll
        for (int i = 0; i < 4; i++) {
            int row = myrow + i * 32;
            const float* ga = A + (size_t)(bm + row) * lda + k0 + myc4;
            uint32_t sa = (uint32_t)__cvta_generic_to_shared(&Asb[row * PAD + myc4]);
            CP16(sa, ga);
            const float* gb = B + (size_t)(bn + row) * ldb + k0 + myc4;
            uint32_t sb = (uint32_t)__cvta_generic_to_shared(&Bsb[row * PAD + myc4]);
            CP16(sb, gb);
        }
        CP_COMMIT();
    };

    int nk = K >> 5;
    issue(0, 0);
    for (int ki = 0; ki < nk; ki++) {
        if (ki + 1 < nk) { issue((ki + 1) << 5, (ki + 1) & 1); CP_WAIT(1); }
        else { CP_WAIT(0); }
        __syncthreads();
        const uint32_t* As = AsBase + (ki & 1) * STG_WORDS;
        const uint32_t* Bs = BsBase + (ki & 1) * STG_WORDS;
#pragma unroll
        for (int ks = 0; ks < 4; ks++) {
            int kk = ks * 8;
            uint32_t af[2][4], bf[8][2];
#pragma unroll
            for (int mi = 0; mi < 2; mi++) {
                int r = wm + mi * 16 + lq;
                af[mi][0] = As[r * PAD + kk + lr];
                af[mi][1] = As[(r + 8) * PAD + kk + lr];
                af[mi][2] = As[r * PAD + kk + lr + 4];
                af[mi][3] = As[(r + 8) * PAD + kk + lr + 4];
            }
#pragma unroll
            for (int ni = 0; ni < 8; ni++) {
                int n = wn + ni * 8 + lq;
                bf[ni][0] = Bs[n * PAD + kk + lr];
                bf[ni][1] = Bs[n * PAD + kk + lr + 4];
            }
#pragma unroll
            for (int mi = 0; mi < 2; mi++)
#pragma unroll
                for (int ni = 0; ni < 8; ni++) mma8(acc[mi][ni], af[mi], bf[ni]);
        }
        __syncthreads();
    }
#pragma unroll
    for (int mi = 0; mi < 2; mi++) {
        int r0 = bm + wm + mi * 16 + lq;
#pragma unroll
        for (int ni = 0; ni < 8; ni++) {
            int col = bn + wn + ni * 8 + 2 * lr;
#pragma unroll
            for (int rr = 0; rr < 2; rr++) {
                int m = r0 + rr * 8;
                float v0 = acc[mi][ni][rr * 2 + 0];
                float v1 = acc[mi][ni][rr * 2 + 1];
                if (EPI == 1) { v0 = fmaxf(v0 + bias[col], 0.f); v1 = fmaxf(v1 + bias[col + 1], 0.f); }
                if (EPI == 2) {
                    v0 += bias[col] + res[(size_t)m * ldres + col];
                    v1 += bias[col + 1] + res[(size_t)m * ldres + col + 1];
                }
                if (EPI == 3) {
                    v0 += res[(size_t)m * ldres + col];
                    v1 += res[(size_t)m * ldres + col + 1];
                }
                if (RND) { v0 = tf32r(v0); v1 = tf32r(v1); }
                *(float2*)(C + (size_t)m * ldc + col) = make_float2(v0, v1);
            }
        }
    }
}

// ---------------------------------------------------------------------------
// Scores: per (b,h) s = (Q K^T)/8 * prior, masked -> attn region (exact fp32).
// q,k already tf32-rounded -> raw copy into smem, no cvt.
// ---------------------------------------------------------------------------
__global__ void __launch_bounds__(256, 2) scores_tc(
    const float* __restrict__ q, const float* __restrict__ k,
    const float* __restrict__ prior, const int* __restrict__ mask,
    float* __restrict__ attn) {
    int z = blockIdx.z;
    int b = z >> 4, h = z & 15;
    const float* A = q + (size_t)b * LL * DD + h * DKK;
    const float* B = k + (size_t)b * LL * DD + h * DKK;
    float* Cp = attn + (size_t)z * LL * LL;
    int bm = blockIdx.y * 128, bn = blockIdx.x * 128;
    __shared__ uint32_t As[128 * PAD];
    __shared__ uint32_t Bs[128 * PAD];
    int tid = threadIdx.x, lane = tid & 31, warp = tid >> 5;
    int wm = (warp & 3) * 32, wn = (warp >> 2) * 64;
    int lq = lane >> 2, lr = lane & 3;
    float acc[2][8][4];
#pragma unroll
    for (int mi = 0; mi < 2; mi++)
#pragma unroll
        for (int ni = 0; ni < 8; ni++)
#pragma unroll
            for (int j = 0; j < 4; j++) acc[mi][ni][j] = 0.f;

    for (int k0 = 0; k0 < DKK; k0 += 32) {
#pragma unroll
        for (int i = 0; i < 4; i++) {
            int idx = tid + i * 256;
            int row = idx >> 3, c4 = (idx & 7) << 2;
            uint4 va = *(const uint4*)(A + (size_t)(bm + row) * DD + k0 + c4);
            *(uint4*)&As[row * PAD + c4] = va;
            uint4 vb = *(const uint4*)(B + (size_t)(bn + row) * DD + k0 + c4);
            *(uint4*)&Bs[row * PAD + c4] = vb;
        }
        __syncthreads();
#pragma unroll
        for (int ks = 0; ks < 4; ks++) {
            int kk = ks * 8;
            uint32_t af[2][4], bf[8][2];
#pragma unroll
            for (int mi = 0; mi < 2; mi++) {
                int r = wm + mi * 16 + lq;
                af[mi][0] = As[r * PAD + kk + lr];
                af[mi][1] = As[(r + 8) * PAD + kk + lr];
                af[mi][2] = As[r * PAD + kk + lr + 4];
                af[mi][3] = As[(r + 8) * PAD + kk + lr + 4];
            }
#pragma unroll
            for (int ni = 0; ni < 8; ni++) {
                int n = wn + ni * 8 + lq;
                bf[ni][0] = Bs[n * PAD + kk + lr];
                bf[ni][1] = Bs[n * PAD + kk + lr + 4];
            }
#pragma unroll
            for (int mi = 0; mi < 2; mi++)
#pragma unroll
                for (int ni = 0; ni < 8; ni++) mma8(acc[mi][ni], af[mi], bf[ni]);
        }
        __syncthreads();
    }
#pragma unroll
    for (int mi = 0; mi < 2; mi++) {
        int r0 = bm + wm + mi * 16 + lq;
#pragma unroll
        for (int ni = 0; ni < 8; ni++) {
            int col = bn + wn + ni * 8 + 2 * lr;
            int m0 = mask[b * LL + col], m1 = mask[b * LL + col + 1];
#pragma unroll
            for (int rr = 0; rr < 2; rr++) {
                int m = r0 + rr * 8;
                const float* prow = prior + ((size_t)b * LL + m) * LL + col;
                float v0 = acc[mi][ni][rr * 2 + 0] * 0.125f * prow[0];
                float v1 = acc[mi][ni][rr * 2 + 1] * 0.125f * prow[1];
                if (m0 == 0) v0 = -1e9f;
                if (m1 == 0) v1 = -1e9f;
                *(float2*)(Cp + (size_t)m * LL + col) = make_float2(v0, v1);
            }
        }
    }
}

// ---------------------------------------------------------------------------
// Softmax (in-place on attn region)
// ---------------------------------------------------------------------------
__global__ void __launch_bounds__(256) softmax_kernel(float* __restrict__ attn) {
    size_t row = blockIdx.x;
    float* p = attn + row * LL;
    int t = threadIdx.x;
    float v[8];
    float mx = -3.4e38f;
#pragma unroll
    for (int i = 0; i < 8; i++) { v[i] = p[t + 256 * i]; mx = fmaxf(mx, v[i]); }
    __shared__ float red[32];
#pragma unroll
    for (int o = 16; o; o >>= 1) mx = fmaxf(mx, __shfl_xor_sync(0xffffffffu, mx, o));
    if ((t & 31) == 0) red[t >> 5] = mx;
    __syncthreads();
    if (t < 32) {
        float z = (t < 8) ? red[t] : -3.4e38f;
#pragma unroll
        for (int o = 4; o; o >>= 1) z = fmaxf(z, __shfl_xor_sync(0xffffffffu, z, o));
        if (t == 0) red[0] = z;
    }
    __syncthreads();
    mx = red[0];
    __syncthreads();
    float s = 0.f;
#pragma unroll
    for (int i = 0; i < 8; i++) { v[i] = expf(v[i] - mx); s += v[i]; }
#pragma unroll
    for (int o = 16; o; o >>= 1) s += __shfl_xor_sync(0xffffffffu, s, o);
    if ((t & 31) == 0) red[t >> 5] = s;
    __syncthreads();
    if (t < 32) {
        float z = (t < 8) ? red[t] : 0.f;
#pragma unroll
        for (int o = 4; o; o >>= 1) z += __shfl_xor_sync(0xffffffffu, z, o);
        if (t == 0) red[0] = z;
    }
    __syncthreads();
    float inv = 1.f / red[0];
#pragma unroll
    for (int i = 0; i < 8; i++) p[t + 256 * i] = v[i] * inv;
}

// ---------------------------------------------------------------------------
// AV: O = attn @ V per (b,h). A (=p) cvt'd at STS; V pre-rounded (raw copy).
// Writes o tf32-rounded (feeds fc GEMM). grid (1,16,64)
// ---------------------------------------------------------------------------
#define VPAD 68
__global__ void __launch_bounds__(256, 2) av_tc(const float* __restrict__ attn,
                                                const float* __restrict__ v,
                                                float* __restrict__ o) {
    int z = blockIdx.z;
    int b = z >> 4, h = z & 15;
    const float* A = attn + (size_t)z * LL * LL;
    const float* Vp = v + (size_t)b * LL * DD + h * DKK;
    float* Cp = o + (size_t)b * LL * DD + h * DKK;
    int bm = blockIdx.y * 128;
    __shared__ uint32_t As[128 * PAD];
    __shared__ uint32_t Bs[32 * VPAD];
    int tid = threadIdx.x, lane = tid & 31, warp = tid >> 5;
    int wm = warp * 16;
    int lq = lane >> 2, lr = lane & 3;
    float acc[8][4];
#pragma unroll
    for (int ni = 0; ni < 8; ni++)
#pragma unroll
        for (int j = 0; j < 4; j++) acc[ni][j] = 0.f;

    for (int k0 = 0; k0 < LL; k0 += 32) {
#pragma unroll
        for (int i = 0; i < 4; i++) {
            int idx = tid + i * 256;
            int row = idx >> 3, c4 = (idx & 7) << 2;
            float4 va = *(const float4*)(A + (size_t)(bm + row) * LL + k0 + c4);
            As[row * PAD + c4 + 0] = f2t(va.x); As[row * PAD + c4 + 1] = f2t(va.y);
            As[row * PAD + c4 + 2] = f2t(va.z); As[row * PAD + c4 + 3] = f2t(va.w);
        }
#pragma unroll
        for (int i = 0; i < 2; i++) {
            int idx = tid + i * 256;
            int krow = idx >> 4, c4 = (idx & 15) << 2;
            uint4 vb = *(const uint4*)(Vp + (size_t)(k0 + krow) * DD + c4);
            *(uint2*)&Bs[krow * VPAD + c4] = make_uint2(vb.x, vb.y);
            *(uint2*)&Bs[krow * VPAD + c4 + 2] = make_uint2(vb.z, vb.w);
        }
        __syncthreads();
#pragma unroll
        for (int ks = 0; ks < 4; ks++) {
            int kk = ks * 8;
            uint32_t af[4], bf[8][2];
            int r = wm + lq;
            af[0] = As[r * PAD + kk + lr];
            af[1] = As[(r + 8) * PAD + kk + lr];
            af[2] = As[r * PAD + kk + lr + 4];
            af[3] = As[(r + 8) * PAD + kk + lr + 4];
#pragma unroll
            for (int ni = 0; ni < 8; ni++) {
                int n = ni * 8 + lq;
                bf[ni][0] = Bs[(kk + lr) * VPAD + n];
                bf[ni][1] = Bs[(kk + lr + 4) * VPAD + n];
            }
#pragma unroll
            for (int ni = 0; ni < 8; ni++) mma8(acc[ni], af, bf[ni]);
        }
        __syncthreads();
    }
    int r0 = bm + wm + lq;
#pragma unroll
    for (int ni = 0; ni < 8; ni++) {
        int col = ni * 8 + 2 * lr;
#pragma unroll
        for (int rr = 0; rr < 2; rr++) {
            int m = r0 + rr * 8;
            *(float2*)(Cp + (size_t)m * DD + col) =
                make_float2(tf32r(acc[ni][rr * 2 + 0]), tf32r(acc[ni][rr * 2 + 1]));
        }
    }
}

// ---------------------------------------------------------------------------
// Launch
// ---------------------------------------------------------------------------
extern "C" void kernel_launch(void* const* d_in, const int* in_sizes, int n_in,
                              void* d_out, int out_size) {
    const float* src    = (const float*)d_in[0];
    const int*   mask   = (const int*)d_in[1];
    const float* prior  = (const float*)d_in[2];
    const float* ln1_g  = (const float*)d_in[3];
    const float* ln1_b  = (const float*)d_in[4];
    const float* wq     = (const float*)d_in[5];
    const float* wk     = (const float*)d_in[6];
    const float* wv     = (const float*)d_in[7];
    const float* fc_w   = (const float*)d_in[8];
    const float* ln2_g  = (const float*)d_in[9];
    const float* ln2_b  = (const float*)d_in[10];
    const float* w1_w   = (const float*)d_in[11];
    const float* w1_b   = (const float*)d_in[12];
    const float* w2_w   = (const float*)d_in[13];
    const float* w2_b   = (const float*)d_in[14];

    float* out = (float*)d_out;
    float* y_out = out;
    float* attn_out = out + ATTN_OFF;

    float *x, *q, *k, *v, *o, *y1, *zz, *hh;
    float *wqt, *wkt, *wvt, *fct, *w1t, *w2t;
    cudaGetSymbolAddress((void**)&x,  g_x);
    cudaGetSymbolAddress((void**)&q,  g_q);
    cudaGetSymbolAddress((void**)&k,  g_k);
    cudaGetSymbolAddress((void**)&v,  g_v);
    cudaGetSymbolAddress((void**)&o,  g_o);
    cudaGetSymbolAddress((void**)&y1, g_y1);
    cudaGetSymbolAddress((void**)&zz, g_z);
    cudaGetSymbolAddress((void**)&hh, g_h);
    cudaGetSymbolAddress((void**)&wqt, g_wqt);
    cudaGetSymbolAddress((void**)&wkt, g_wkt);
    cudaGetSymbolAddress((void**)&wvt, g_wvt);
    cudaGetSymbolAddress((void**)&fct, g_fct);
    cudaGetSymbolAddress((void**)&w1t, g_w1t);
    cudaGetSymbolAddress((void**)&w2t, g_w2t);

    const int GSMEM = 4 * 4 * STG_WORDS;  // 73728 bytes
    static bool attr_set = false;
    if (!attr_set) {
        cudaFuncSetAttribute((const void*)gemm_tc<0, true>,  cudaFuncAttributeMaxDynamicSharedMemorySize, GSMEM);
        cudaFuncSetAttribute((const void*)gemm_tc<1, true>,  cudaFuncAttributeMaxDynamicSharedMemorySize, GSMEM);
        cudaFuncSetAttribute((const void*)gemm_tc<2, false>, cudaFuncAttributeMaxDynamicSharedMemorySize, GSMEM);
        cudaFuncSetAttribute((const void*)gemm_tc<3, false>, cudaFuncAttributeMaxDynamicSharedMemorySize, GSMEM);
        attr_set = true;
    }

    // Pre-round weights to tf32 (bit-identical to converting at use time)
    const int NW1 = DD * DD / 4;          // 262144 float4s
    const int NW2 = DFF * DD / 4;         // 1048576 float4s
    cvt_kernel<<<(NW1 + 255) / 256, 256>>>(wq, wqt, NW1);
    cvt_kernel<<<(NW1 + 255) / 256, 256>>>(wk, wkt, NW1);
    cvt_kernel<<<(NW1 + 255) / 256, 256>>>(wv, wvt, NW1);
    cvt_kernel<<<(NW1 + 255) / 256, 256>>>(fc_w, fct, NW1);
    cvt_kernel<<<(NW2 + 255) / 256, 256>>>(w1_w, w1t, NW2);
    cvt_kernel<<<(NW2 + 255) / 256, 256>>>(w2_w, w2t, NW2);

    ln_kernel<<<MROWS, 256>>>(src, ln1_g, ln1_b, x);

    dim3 gproj(DD / 128, MROWS / 128);
    gemm_tc<0, true><<<gproj, 256, GSMEM>>>(x, DD, wqt, DD, q, DD, DD, nullptr, nullptr, 0);
    gemm_tc<0, true><<<gproj, 256, GSMEM>>>(x, DD, wkt, DD, k, DD, DD, nullptr, nullptr, 0);
    gemm_tc<0, true><<<gproj, 256, GSMEM>>>(x, DD, wvt, DD, v, DD, DD, nullptr, nullptr, 0);

    scores_tc<<<dim3(LL / 128, LL / 128, BB * HH), 256>>>(q, k, prior, mask, attn_out);

    softmax_kernel<<<BB * HH * LL, 256>>>(attn_out);

    av_tc<<<dim3(1, LL / 128, BB * HH), 256>>>(attn_out, v, o);

    gemm_tc<3, false><<<gproj, 256, GSMEM>>>(o, DD, fct, DD, y1, DD, DD, nullptr, src, DD);

    ln_kernel<<<MROWS, 256>>>(y1, ln2_g, ln2_b, zz);

    gemm_tc<1, true><<<dim3(DFF / 128, MROWS / 128), 256, GSMEM>>>(zz, DD, w1t, DD, hh, DFF, DD, w1_b, nullptr, 0);

    gemm_tc<2, false><<<gproj, 256, GSMEM>>>(hh, DFF, w2t, DFF, y_out, DD, DFF, w2_b, y1, DD);
}

// round 9
// speedup vs baseline: 1.3212x; 1.1113x over previous
#include <cuda_runtime.h>
#include <cuda_bf16.h>
#include <cstdint>

#define BB 4
#define LL 2048
#define DD 1024
#define HH 16
#define DKK 64
#define DFF 4096
#define MROWS (BB*LL)
#define ATTN_OFF ((size_t)MROWS*DD)
#define PAD 36
#define STG_WORDS (128*PAD)
#define VPAD 68

// Scratch
__device__ float g_x[(size_t)MROWS*DD];
__device__ float g_q[(size_t)MROWS*DD];
__device__ float g_k[(size_t)MROWS*DD];
__device__ float g_v[(size_t)MROWS*DD];
__device__ float g_o[(size_t)MROWS*DD];
__device__ float g_y1[(size_t)MROWS*DD];
__device__ float g_z[(size_t)MROWS*DD];
__device__ float g_h[(size_t)MROWS*DFF];
__device__ float g_rpart[(size_t)BB*HH*LL*16];   // per-(z,row) partial rowsums, 16 bn-tiles
// tf32-rounded weight copies
__device__ float g_wqt[(size_t)DD*DD];
__device__ float g_wkt[(size_t)DD*DD];
__device__ float g_wvt[(size_t)DD*DD];
__device__ float g_fct[(size_t)DD*DD];
__device__ float g_w1t[(size_t)DFF*DD];
__device__ float g_w2t[(size_t)DD*DFF];

__device__ __forceinline__ float tf32r(float x) {
    uint32_t u; asm("cvt.rna.tf32.f32 %0, %1;" : "=r"(u) : "f"(x));
    return __uint_as_float(u);
}
__device__ __forceinline__ uint32_t f2t(float x) {
    uint32_t u; asm("cvt.rna.tf32.f32 %0, %1;" : "=r"(u) : "f"(x)); return u;
}
__device__ __forceinline__ void mma8(float* c, const uint32_t* a, const uint32_t* b) {
    asm volatile(
        "mma.sync.aligned.m16n8k8.row.col.f32.tf32.tf32.f32 "
        "{%0,%1,%2,%3},{%4,%5,%6,%7},{%8,%9},{%0,%1,%2,%3};"
        : "+f"(c[0]), "+f"(c[1]), "+f"(c[2]), "+f"(c[3])
        : "r"(a[0]), "r"(a[1]), "r"(a[2]), "r"(a[3]), "r"(b[0]), "r"(b[1]));
}
#define CP16(dst_u32, src_ptr) \
    asm volatile("cp.async.cg.shared.global [%0], [%1], 16;\n" :: "r"(dst_u32), "l"(src_ptr))
#define CP_COMMIT() asm volatile("cp.async.commit_group;\n" ::: "memory")
#define CP_WAIT(n)  asm volatile("cp.async.wait_group %0;\n" :: "n"(n) : "memory")

// ---------------------------------------------------------------------------
// Weight pre-round
// ---------------------------------------------------------------------------
__global__ void __launch_bounds__(256) cvt_kernel(const float* __restrict__ in,
                                                  float* __restrict__ out, int n4) {
    int i = blockIdx.x * 256 + threadIdx.x;
    if (i < n4) {
        float4 v = ((const float4*)in)[i];
        v.x = tf32r(v.x); v.y = tf32r(v.y); v.z = tf32r(v.z); v.w = tf32r(v.w);
        ((float4*)out)[i] = v;
    }
}

// ---------------------------------------------------------------------------
// LayerNorm; output tf32-rounded (only feeds GEMM A operands)
// ---------------------------------------------------------------------------
__global__ void __launch_bounds__(256) ln_kernel(const float* __restrict__ in,
                                                 const float* __restrict__ gamma,
                                                 const float* __restrict__ beta,
                                                 float* __restrict__ out) {
    int row = blockIdx.x;
    const float* x = in + (size_t)row * DD;
    float* y = out + (size_t)row * DD;
    int t = threadIdx.x;
    float v[4];
    float s = 0.f;
#pragma unroll
    for (int i = 0; i < 4; i++) { v[i] = x[t + 256 * i]; s += v[i]; }
    __shared__ float red[32];
#pragma unroll
    for (int o = 16; o; o >>= 1) s += __shfl_xor_sync(0xffffffffu, s, o);
    if ((t & 31) == 0) red[t >> 5] = s;
    __syncthreads();
    if (t < 32) {
        float z = (t < 8) ? red[t] : 0.f;
#pragma unroll
        for (int o = 4; o; o >>= 1) z += __shfl_xor_sync(0xffffffffu, z, o);
        if (t == 0) red[0] = z;
    }
    __syncthreads();
    float mu = red[0] * (1.f / DD);
    __syncthreads();
    float s2 = 0.f;
#pragma unroll
    for (int i = 0; i < 4; i++) { float d = v[i] - mu; s2 += d * d; }
#pragma unroll
    for (int o = 16; o; o >>= 1) s2 += __shfl_xor_sync(0xffffffffu, s2, o);
    if ((t & 31) == 0) red[t >> 5] = s2;
    __syncthreads();
    if (t < 32) {
        float z = (t < 8) ? red[t] : 0.f;
#pragma unroll
        for (int o = 4; o; o >>= 1) z += __shfl_xor_sync(0xffffffffu, z, o);
        if (t == 0) red[0] = z;
    }
    __syncthreads();
    float rstd = rsqrtf(red[0] * (1.f / DD) + 1e-6f);
#pragma unroll
    for (int i = 0; i < 4; i++) {
        int c = t + 256 * i;
        y[c] = tf32r((v[i] - mu) * rstd * gamma[c] + beta[c]);
    }
}

// ---------------------------------------------------------------------------
// tf32 GEMM, cp.async 2-stage, no cvt (inputs pre-rounded).
// ---------------------------------------------------------------------------
template <int EPI, bool RND>
__global__ void __launch_bounds__(256, 2) gemm_tc(
    const float* __restrict__ A, int lda,
    const float* __restrict__ B, int ldb,
    float* __restrict__ C, int ldc, int K,
    const float* __restrict__ bias,
    const float* __restrict__ res, int ldres) {
    extern __shared__ uint32_t sh[];
    uint32_t* AsBase = sh;
    uint32_t* BsBase = sh + 2 * STG_WORDS;
    int bm = blockIdx.y * 128, bn = blockIdx.x * 128;
    int tid = threadIdx.x, lane = tid & 31, warp = tid >> 5;
    int wm = (warp & 3) * 32, wn = (warp >> 2) * 64;
    int lq = lane >> 2, lr = lane & 3;
    float acc[2][8][4];
#pragma unroll
    for (int mi = 0; mi < 2; mi++)
#pragma unroll
        for (int ni = 0; ni < 8; ni++)
#pragma unroll
            for (int j = 0; j < 4; j++) acc[mi][ni][j] = 0.f;

    int myrow = tid >> 3;
    int myc4 = (tid & 7) << 2;

    auto issue = [&](int k0, int buf) {
        uint32_t* Asb = AsBase + buf * STG_WORDS;
        uint32_t* Bsb = BsBase + buf * STG_WORDS;
#pragma unroll
        for (int i = 0; i < 4; i++) {
            int row = myrow + i * 32;
            const float* ga = A + (size_t)(bm + row) * lda + k0 + myc4;
            uint32_t sa = (uint32_t)__cvta_generic_to_shared(&Asb[row * PAD + myc4]);
            CP16(sa, ga);
            const float* gb = B + (size_t)(bn + row) * ldb + k0 + myc4;
            uint32_t sb = (uint32_t)__cvta_generic_to_shared(&Bsb[row * PAD + myc4]);
            CP16(sb, gb);
        }
        CP_COMMIT();
    };

    int nk = K >> 5;
    issue(0, 0);
    for (int ki = 0; ki < nk; ki++) {
        if (ki + 1 < nk) { issue((ki + 1) << 5, (ki + 1) & 1); CP_WAIT(1); }
        else { CP_WAIT(0); }
        __syncthreads();
        const uint32_t* As = AsBase + (ki & 1) * STG_WORDS;
        const uint32_t* Bs = BsBase + (ki & 1) * STG_WORDS;
#pragma unroll
        for (int ks = 0; ks < 4; ks++) {
            int kk = ks * 8;
            uint32_t af[2][4], bf[8][2];
#pragma unroll
            for (int mi = 0; mi < 2; mi++) {
                int r = wm + mi * 16 + lq;
                af[mi][0] = As[r * PAD + kk + lr];
                af[mi][1] = As[(r + 8) * PAD + kk + lr];
                af[mi][2] = As[r * PAD + kk + lr + 4];
                af[mi][3] = As[(r + 8) * PAD + kk + lr + 4];
            }
#pragma unroll
            for (int ni = 0; ni < 8; ni++) {
                int n = wn + ni * 8 + lq;
                bf[ni][0] = Bs[n * PAD + kk + lr];
                bf[ni][1] = Bs[n * PAD + kk + lr + 4];
            }
#pragma unroll
            for (int mi = 0; mi < 2; mi++)
#pragma unroll
                for (int ni = 0; ni < 8; ni++) mma8(acc[mi][ni], af[mi], bf[ni]);
        }
        __syncthreads();
    }
#pragma unroll
    for (int mi = 0; mi < 2; mi++) {
        int r0 = bm + wm + mi * 16 + lq;
#pragma unroll
        for (int ni = 0; ni < 8; ni++) {
            int col = bn + wn + ni * 8 + 2 * lr;
#pragma unroll
            for (int rr = 0; rr < 2; rr++) {
                int m = r0 + rr * 8;
                float v0 = acc[mi][ni][rr * 2 + 0];
                float v1 = acc[mi][ni][rr * 2 + 1];
                if (EPI == 1) { v0 = fmaxf(v0 + bias[col], 0.f); v1 = fmaxf(v1 + bias[col + 1], 0.f); }
                if (EPI == 2) {
                    v0 += bias[col] + res[(size_t)m * ldres + col];
                    v1 += bias[col + 1] + res[(size_t)m * ldres + col + 1];
                }
                if (EPI == 3) {
                    v0 += res[(size_t)m * ldres + col];
                    v1 += res[(size_t)m * ldres + col + 1];
                }
                if (RND) { v0 = tf32r(v0); v1 = tf32r(v1); }
                *(float2*)(C + (size_t)m * ldc + col) = make_float2(v0, v1);
            }
        }
    }
}

// ---------------------------------------------------------------------------
// Scores: per (b,h) e = exp((Q K^T)/8 * prior, masked) -> attn region.
// Writes per-tile partial rowsums to g_rpart[z,m,bnt] (no atomics).
// grid (16,16,64)
// ---------------------------------------------------------------------------
__global__ void __launch_bounds__(256, 2) scores_tc(
    const float* __restrict__ q, const float* __restrict__ k,
    const float* __restrict__ prior, const int* __restrict__ mask,
    float* __restrict__ attn, float* __restrict__ rpart) {
    int z = blockIdx.z;
    int b = z >> 4, h = z & 15;
    const float* A = q + (size_t)b * LL * DD + h * DKK;
    const float* B = k + (size_t)b * LL * DD + h * DKK;
    float* Cp = attn + (size_t)z * LL * LL;
    int bm = blockIdx.y * 128, bn = blockIdx.x * 128;
    __shared__ uint32_t As[128 * PAD];
    __shared__ uint32_t Bs[128 * PAD];
    __shared__ float rsh[128][2];
    int tid = threadIdx.x, lane = tid & 31, warp = tid >> 5;
    int wm = (warp & 3) * 32, wn2 = warp >> 2;
    int wn = wn2 * 64;
    int lq = lane >> 2, lr = lane & 3;
    float acc[2][8][4];
#pragma unroll
    for (int mi = 0; mi < 2; mi++)
#pragma unroll
        for (int ni = 0; ni < 8; ni++)
#pragma unroll
            for (int j = 0; j < 4; j++) acc[mi][ni][j] = 0.f;

    for (int k0 = 0; k0 < DKK; k0 += 32) {
#pragma unroll
        for (int i = 0; i < 4; i++) {
            int idx = tid + i * 256;
            int row = idx >> 3, c4 = (idx & 7) << 2;
            uint4 va = *(const uint4*)(A + (size_t)(bm + row) * DD + k0 + c4);
            *(uint4*)&As[row * PAD + c4] = va;
            uint4 vb = *(const uint4*)(B + (size_t)(bn + row) * DD + k0 + c4);
            *(uint4*)&Bs[row * PAD + c4] = vb;
        }
        __syncthreads();
#pragma unroll
        for (int ks = 0; ks < 4; ks++) {
            int kk = ks * 8;
            uint32_t af[2][4], bf[8][2];
#pragma unroll
            for (int mi = 0; mi < 2; mi++) {
                int r = wm + mi * 16 + lq;
                af[mi][0] = As[r * PAD + kk + lr];
                af[mi][1] = As[(r + 8) * PAD + kk + lr];
                af[mi][2] = As[r * PAD + kk + lr + 4];
                af[mi][3] = As[(r + 8) * PAD + kk + lr + 4];
            }
#pragma unroll
            for (int ni = 0; ni < 8; ni++) {
                int n = wn + ni * 8 + lq;
                bf[ni][0] = Bs[n * PAD + kk + lr];
                bf[ni][1] = Bs[n * PAD + kk + lr + 4];
            }
#pragma unroll
            for (int mi = 0; mi < 2; mi++)
#pragma unroll
                for (int ni = 0; ni < 8; ni++) mma8(acc[mi][ni], af[mi], bf[ni]);
        }
        __syncthreads();
    }
#pragma unroll
    for (int mi = 0; mi < 2; mi++) {
        int r0 = bm + wm + mi * 16 + lq;
        float rsum[2] = {0.f, 0.f};
#pragma unroll
        for (int ni = 0; ni < 8; ni++) {
            int col = bn + wn + ni * 8 + 2 * lr;
            int m0 = mask[b * LL + col], m1 = mask[b * LL + col + 1];
#pragma unroll
            for (int rr = 0; rr < 2; rr++) {
                int m = r0 + rr * 8;
                const float* prow = prior + ((size_t)b * LL + m) * LL + col;
                float v0 = acc[mi][ni][rr * 2 + 0] * 0.125f * prow[0];
                float v1 = acc[mi][ni][rr * 2 + 1] * 0.125f * prow[1];
                if (m0 == 0) v0 = -1e9f;
                if (m1 == 0) v1 = -1e9f;
                float e0 = expf(v0), e1 = expf(v1);
                rsum[rr] += e0 + e1;
                *(float2*)(Cp + (size_t)m * LL + col) = make_float2(e0, e1);
            }
        }
#pragma unroll
        for (int rr = 0; rr < 2; rr++) {
            float s = rsum[rr];
            s += __shfl_xor_sync(0xffffffffu, s, 1);
            s += __shfl_xor_sync(0xffffffffu, s, 2);
            if (lr == 0) rsh[wm + mi * 16 + lq + rr * 8][wn2] = s;
        }
    }
    __syncthreads();
    if (tid < 128)
        rpart[((size_t)z * LL + bm + tid) * 16 + blockIdx.x] = rsh[tid][0] + rsh[tid][1];
}

// ---------------------------------------------------------------------------
// AV fused normalize: reads e, writes p = e*inv to attn (final output),
// computes O = (e @ V) * inv per (b,h). cp.async 2-stage. grid (1,16,64)
// ---------------------------------------------------------------------------
__global__ void __launch_bounds__(256, 2) av_tc(float* __restrict__ attn,
                                                const float* __restrict__ v,
                                                const float* __restrict__ rpart,
                                                float* __restrict__ o) {
    extern __shared__ uint32_t sh[];
    uint32_t* AsBase = sh;                               // 2 x 128*PAD
    uint32_t* BsBase = sh + 2 * STG_WORDS;               // 2 x 32*VPAD
    float* invl = (float*)(sh + 2 * STG_WORDS + 2 * 32 * VPAD);  // 128
    int z = blockIdx.z;
    int b = z >> 4, h = z & 15;
    float* A = attn + (size_t)z * LL * LL;
    const float* Vp = v + (size_t)b * LL * DD + h * DKK;
    float* Cp = o + (size_t)b * LL * DD + h * DKK;
    int bm = blockIdx.y * 128;
    int tid = threadIdx.x, lane = tid & 31, warp = tid >> 5;
    int wm = warp * 16;
    int lq = lane >> 2, lr = lane & 3;

    if (tid < 128) {
        const float* rp = rpart + ((size_t)z * LL + bm + tid) * 16;
        float s = 0.f;
#pragma unroll
        for (int i = 0; i < 16; i++) s += rp[i];
        invl[tid] = 1.f / s;
    }

    auto issue = [&](int k0, int buf) {
        uint32_t* Asb = AsBase + buf * STG_WORDS;
        uint32_t* Bsb = BsBase + buf * (32 * VPAD);
#pragma unroll
        for (int i = 0; i < 4; i++) {
            int idx = tid + i * 256;
            int row = idx >> 3, c4 = (idx & 7) << 2;
            const float* ga = A + (size_t)(bm + row) * LL + k0 + c4;
            uint32_t sa = (uint32_t)__cvta_generic_to_shared(&Asb[row * PAD + c4]);
            CP16(sa, ga);
        }
#pragma unroll
        for (int i = 0; i < 2; i++) {
            int idx = tid + i * 256;
            int krow = idx >> 4, c4 = (idx & 15) << 2;
            const float* gb = Vp + (size_t)(k0 + krow) * DD + c4;
            uint32_t sb = (uint32_t)__cvta_generic_to_shared(&Bsb[krow * VPAD + c4]);
            CP16(sb, gb);
        }
        CP_COMMIT();
    };

    float acc[8][4];
#pragma unroll
    for (int ni = 0; ni < 8; ni++)
#pragma unroll
        for (int j = 0; j < 4; j++) acc[ni][j] = 0.f;

    const int nk = LL / 32;   // 64
    issue(0, 0);
    for (int ki = 0; ki < nk; ki++) {
        if (ki + 1 < nk) { issue((ki + 1) << 5, (ki + 1) & 1); CP_WAIT(1); }
        else { CP_WAIT(0); }
        __syncthreads();
        const uint32_t* As = AsBase + (ki & 1) * STG_WORDS;
        const uint32_t* Bs = BsBase + (ki & 1) * (32 * VPAD);
        int k0 = ki << 5;
        // write normalized p back to attn (overlaps with MMA below)
#pragma unroll
        for (int i = 0; i < 4; i++) {
            int idx = tid + i * 256;
            int row = idx >> 3, c4 = (idx & 7) << 2;
            float4 e = *(const float4*)&As[row * PAD + c4];
            float il = invl[row];
            e.x *= il; e.y *= il; e.z *= il; e.w *= il;
            *(float4*)(A + (size_t)(bm + row) * LL + k0 + c4) = e;
        }
#pragma unroll
        for (int ks = 0; ks < 4; ks++) {
            int kk = ks * 8;
            uint32_t af[4], bf[8][2];
            int r = wm + lq;
            af[0] = f2t(__uint_as_float(As[r * PAD + kk + lr]));
            af[1] = f2t(__uint_as_float(As[(r + 8) * PAD + kk + lr]));
            af[2] = f2t(__uint_as_float(As[r * PAD + kk + lr + 4]));
            af[3] = f2t(__uint_as_float(As[(r + 8) * PAD + kk + lr + 4]));
#pragma unroll
            for (int ni = 0; ni < 8; ni++) {
                int n = ni * 8 + lq;
                bf[ni][0] = Bs[(kk + lr) * VPAD + n];
                bf[ni][1] = Bs[(kk + lr + 4) * VPAD + n];
            }
#pragma unroll
            for (int ni = 0; ni < 8; ni++) mma8(acc[ni], af, bf[ni]);
        }
        __syncthreads();
    }
    int mloc = wm + lq;
#pragma unroll
    for (int ni = 0; ni < 8; ni++) {
        int col = ni * 8 + 2 * lr;
#pragma unroll
        for (int rr = 0; rr < 2; rr++) {
            int m = bm + mloc + rr * 8;
            float il = invl[mloc + rr * 8];
            *(float2*)(Cp + (size_t)m * DD + col) =
                make_float2(tf32r(acc[ni][rr * 2 + 0] * il), tf32r(acc[ni][rr * 2 + 1] * il));
        }
    }
}

// ---------------------------------------------------------------------------
// Launch
// ---------------------------------------------------------------------------
extern "C" void kernel_launch(void* const* d_in, const int* in_sizes, int n_in,
                              void* d_out, int out_size) {
    const float* src    = (const float*)d_in[0];
    const int*   mask   = (const int*)d_in[1];
    const float* prior  = (const float*)d_in[2];
    const float* ln1_g  = (const float*)d_in[3];
    const float* ln1_b  = (const float*)d_in[4];
    const float* wq     = (const float*)d_in[5];
    const float* wk     = (const float*)d_in[6];
    const float* wv     = (const float*)d_in[7];
    const float* fc_w   = (const float*)d_in[8];
    const float* ln2_g  = (const float*)d_in[9];
    const float* ln2_b  = (const float*)d_in[10];
    const float* w1_w   = (const float*)d_in[11];
    const float* w1_b   = (const float*)d_in[12];
    const float* w2_w   = (const float*)d_in[13];
    const float* w2_b   = (const float*)d_in[14];

    float* out = (float*)d_out;
    float* y_out = out;
    float* attn_out = out + ATTN_OFF;

    float *x, *q, *k, *v, *o, *y1, *zz, *hh, *rp;
    float *wqt, *wkt, *wvt, *fct, *w1t, *w2t;
    cudaGetSymbolAddress((void**)&x,  g_x);
    cudaGetSymbolAddress((void**)&q,  g_q);
    cudaGetSymbolAddress((void**)&k,  g_k);
    cudaGetSymbolAddress((void**)&v,  g_v);
    cudaGetSymbolAddress((void**)&o,  g_o);
    cudaGetSymbolAddress((void**)&y1, g_y1);
    cudaGetSymbolAddress((void**)&zz, g_z);
    cudaGetSymbolAddress((void**)&hh, g_h);
    cudaGetSymbolAddress((void**)&rp, g_rpart);
    cudaGetSymbolAddress((void**)&wqt, g_wqt);
    cudaGetSymbolAddress((void**)&wkt, g_wkt);
    cudaGetSymbolAddress((void**)&wvt, g_wvt);
    cudaGetSymbolAddress((void**)&fct, g_fct);
    cudaGetSymbolAddress((void**)&w1t, g_w1t);
    cudaGetSymbolAddress((void**)&w2t, g_w2t);

    const int GSMEM = 4 * 4 * STG_WORDS;                       // 73728 B
    const int AVSMEM = 4 * (2 * STG_WORDS + 2 * 32 * VPAD) + 512;  // ~91648 B
    static bool attr_set = false;
    if (!attr_set) {
        cudaFuncSetAttribute((const void*)gemm_tc<0, true>,  cudaFuncAttributeMaxDynamicSharedMemorySize, GSMEM);
        cudaFuncSetAttribute((const void*)gemm_tc<1, true>,  cudaFuncAttributeMaxDynamicSharedMemorySize, GSMEM);
        cudaFuncSetAttribute((const void*)gemm_tc<2, false>, cudaFuncAttributeMaxDynamicSharedMemorySize, GSMEM);
        cudaFuncSetAttribute((const void*)gemm_tc<3, false>, cudaFuncAttributeMaxDynamicSharedMemorySize, GSMEM);
        cudaFuncSetAttribute((const void*)av_tc, cudaFuncAttributeMaxDynamicSharedMemorySize, AVSMEM);
        attr_set = true;
    }

    // Pre-round weights to tf32
    const int NW1 = DD * DD / 4;
    const int NW2 = DFF * DD / 4;
    cvt_kernel<<<(NW1 + 255) / 256, 256>>>(wq, wqt, NW1);
    cvt_kernel<<<(NW1 + 255) / 256, 256>>>(wk, wkt, NW1);
    cvt_kernel<<<(NW1 + 255) / 256, 256>>>(wv, wvt, NW1);
    cvt_kernel<<<(NW1 + 255) / 256, 256>>>(fc_w, fct, NW1);
    cvt_kernel<<<(NW2 + 255) / 256, 256>>>(w1_w, w1t, NW2);
    cvt_kernel<<<(NW2 + 255) / 256, 256>>>(w2_w, w2t, NW2);

    ln_kernel<<<MROWS, 256>>>(src, ln1_g, ln1_b, x);

    dim3 gproj(DD / 128, MROWS / 128);
    gemm_tc<0, true><<<gproj, 256, GSMEM>>>(x, DD, wqt, DD, q, DD, DD, nullptr, nullptr, 0);
    gemm_tc<0, true><<<gproj, 256, GSMEM>>>(x, DD, wkt, DD, k, DD, DD, nullptr, nullptr, 0);
    gemm_tc<0, true><<<gproj, 256, GSMEM>>>(x, DD, wvt, DD, v, DD, DD, nullptr, nullptr, 0);

    scores_tc<<<dim3(LL / 128, LL / 128, BB * HH), 256>>>(q, k, prior, mask, attn_out, rp);

    av_tc<<<dim3(1, LL / 128, BB * HH), 256, AVSMEM>>>(attn_out, v, rp, o);

    gemm_tc<3, false><<<gproj, 256, GSMEM>>>(o, DD, fct, DD, y1, DD, DD, nullptr, src, DD);

    ln_kernel<<<MROWS, 256>>>(y1, ln2_g, ln2_b, zz);

    gemm_tc<1, true><<<dim3(DFF / 128, MROWS / 128), 256, GSMEM>>>(zz, DD, w1t, DD, hh, DFF, DD, w1_b, nullptr, 0);

    gemm_tc<2, false><<<gproj, 256, GSMEM>>>(hh, DFF, w2t, DFF, y_out, DD, DFF, w2_b, y1, DD);
}

// round 10
// speedup vs baseline: 1.3675x; 1.0350x over previous
#include <cuda_runtime.h>
#include <cuda_bf16.h>
#include <cstdint>

#define BB 4
#define LL 2048
#define DD 1024
#define HH 16
#define DKK 64
#define DFF 4096
#define MROWS (BB*LL)
#define ATTN_OFF ((size_t)MROWS*DD)
#define PAD 36
#define STG_WORDS (128*PAD)
#define VPAD 68
#define QLD (3*DD)   // merged qkv row stride

// Scratch
__device__ float g_x[(size_t)MROWS*DD];
__device__ float g_qkv[(size_t)MROWS*QLD];
__device__ float g_o[(size_t)MROWS*DD];
__device__ float g_y1[(size_t)MROWS*DD];
__device__ float g_z[(size_t)MROWS*DD];
__device__ float g_h[(size_t)MROWS*DFF];
__device__ float g_rpart[(size_t)BB*HH*LL*16];
// tf32-rounded weight copies
__device__ float g_wqkvt[(size_t)3*DD*DD];
__device__ float g_fct[(size_t)DD*DD];
__device__ float g_w1t[(size_t)DFF*DD];
__device__ float g_w2t[(size_t)DD*DFF];

__device__ __forceinline__ float tf32r(float x) {
    uint32_t u; asm("cvt.rna.tf32.f32 %0, %1;" : "=r"(u) : "f"(x));
    return __uint_as_float(u);
}
__device__ __forceinline__ uint32_t f2t(float x) {
    uint32_t u; asm("cvt.rna.tf32.f32 %0, %1;" : "=r"(u) : "f"(x)); return u;
}
__device__ __forceinline__ void mma8(float* c, const uint32_t* a, const uint32_t* b) {
    asm volatile(
        "mma.sync.aligned.m16n8k8.row.col.f32.tf32.tf32.f32 "
        "{%0,%1,%2,%3},{%4,%5,%6,%7},{%8,%9},{%0,%1,%2,%3};"
        : "+f"(c[0]), "+f"(c[1]), "+f"(c[2]), "+f"(c[3])
        : "r"(a[0]), "r"(a[1]), "r"(a[2]), "r"(a[3]), "r"(b[0]), "r"(b[1]));
}
__device__ __forceinline__ void ldsm4(uint32_t* r, uint32_t saddr) {
    asm volatile("ldmatrix.sync.aligned.m8n8.x4.shared.b16 {%0,%1,%2,%3}, [%4];"
        : "=r"(r[0]), "=r"(r[1]), "=r"(r[2]), "=r"(r[3]) : "r"(saddr));
}
#define CP16(dst_u32, src_ptr) \
    asm volatile("cp.async.cg.shared.global [%0], [%1], 16;\n" :: "r"(dst_u32), "l"(src_ptr))
#define CP_COMMIT() asm volatile("cp.async.commit_group;\n" ::: "memory")
#define CP_WAIT(n)  asm volatile("cp.async.wait_group %0;\n" :: "n"(n) : "memory")

// ---------------------------------------------------------------------------
// Weight pre-round
// ---------------------------------------------------------------------------
__global__ void __launch_bounds__(256) cvt_kernel(const float* __restrict__ in,
                                                  float* __restrict__ out, int n4) {
    int i = blockIdx.x * 256 + threadIdx.x;
    if (i < n4) {
        float4 v = ((const float4*)in)[i];
        v.x = tf32r(v.x); v.y = tf32r(v.y); v.z = tf32r(v.z); v.w = tf32r(v.w);
        ((float4*)out)[i] = v;
    }
}

// ---------------------------------------------------------------------------
// LayerNorm; output tf32-rounded
// ---------------------------------------------------------------------------
__global__ void __launch_bounds__(256) ln_kernel(const float* __restrict__ in,
                                                 const float* __restrict__ gamma,
                                                 const float* __restrict__ beta,
                                                 float* __restrict__ out) {
    int row = blockIdx.x;
    const float* x = in + (size_t)row * DD;
    float* y = out + (size_t)row * DD;
    int t = threadIdx.x;
    float v[4];
    float s = 0.f;
#pragma unroll
    for (int i = 0; i < 4; i++) { v[i] = x[t + 256 * i]; s += v[i]; }
    __shared__ float red[32];
#pragma unroll
    for (int o = 16; o; o >>= 1) s += __shfl_xor_sync(0xffffffffu, s, o);
    if ((t & 31) == 0) red[t >> 5] = s;
    __syncthreads();
    if (t < 32) {
        float z = (t < 8) ? red[t] : 0.f;
#pragma unroll
        for (int o = 4; o; o >>= 1) z += __shfl_xor_sync(0xffffffffu, z, o);
        if (t == 0) red[0] = z;
    }
    __syncthreads();
    float mu = red[0] * (1.f / DD);
    __syncthreads();
    float s2 = 0.f;
#pragma unroll
    for (int i = 0; i < 4; i++) { float d = v[i] - mu; s2 += d * d; }
#pragma unroll
    for (int o = 16; o; o >>= 1) s2 += __shfl_xor_sync(0xffffffffu, s2, o);
    if ((t & 31) == 0) red[t >> 5] = s2;
    __syncthreads();
    if (t < 32) {
        float z = (t < 8) ? red[t] : 0.f;
#pragma unroll
        for (int o = 4; o; o >>= 1) z += __shfl_xor_sync(0xffffffffu, z, o);
        if (t == 0) red[0] = z;
    }
    __syncthreads();
    float rstd = rsqrtf(red[0] * (1.f / DD) + 1e-6f);
#pragma unroll
    for (int i = 0; i < 4; i++) {
        int c = t + 256 * i;
        y[c] = tf32r((v[i] - mu) * rstd * gamma[c] + beta[c]);
    }
}

// ---------------------------------------------------------------------------
// tf32 GEMM, cp.async 2-stage + ldmatrix fragment loads.
// ---------------------------------------------------------------------------
template <int EPI, bool RND>
__global__ void __launch_bounds__(256, 2) gemm_tc(
    const float* __restrict__ A, int lda,
    const float* __restrict__ B, int ldb,
    float* __restrict__ C, int ldc, int K,
    const float* __restrict__ bias,
    const float* __restrict__ res, int ldres) {
    extern __shared__ uint32_t sh[];
    uint32_t* AsBase = sh;
    uint32_t* BsBase = sh + 2 * STG_WORDS;
    int bm = blockIdx.y * 128, bn = blockIdx.x * 128;
    int tid = threadIdx.x, lane = tid & 31, warp = tid >> 5;
    int wm = (warp & 3) * 32, wn = (warp >> 2) * 64;
    int lq = lane >> 2, lr = lane & 3;
    // ldmatrix per-lane address components
    int a_r = lane & 15, a_c = (lane >> 4) << 2;          // A tiles: rows, col-half
    int b_r = (lane & 7) + ((lane & 16) ? 8 : 0);         // B tiles
    int b_c = (lane & 8) ? 4 : 0;
    uint32_t sA0 = (uint32_t)__cvta_generic_to_shared(AsBase);
    uint32_t sB0 = (uint32_t)__cvta_generic_to_shared(BsBase);
    float acc[2][8][4];
#pragma unroll
    for (int mi = 0; mi < 2; mi++)
#pragma unroll
        for (int ni = 0; ni < 8; ni++)
#pragma unroll
            for (int j = 0; j < 4; j++) acc[mi][ni][j] = 0.f;

    int myrow = tid >> 3;
    int myc4 = (tid & 7) << 2;

    auto issue = [&](int k0, int buf) {
        uint32_t* Asb = AsBase + buf * STG_WORDS;
        uint32_t* Bsb = BsBase + buf * STG_WORDS;
#pragma unroll
        for (int i = 0; i < 4; i++) {
            int row = myrow + i * 32;
            const float* ga = A + (size_t)(bm + row) * lda + k0 + myc4;
            uint32_t sa = (uint32_t)__cvta_generic_to_shared(&Asb[row * PAD + myc4]);
            CP16(sa, ga);
            const float* gb = B + (size_t)(bn + row) * ldb + k0 + myc4;
            uint32_t sb = (uint32_t)__cvta_generic_to_shared(&Bsb[row * PAD + myc4]);
            CP16(sb, gb);
        }
        CP_COMMIT();
    };

    int nk = K >> 5;
    issue(0, 0);
    for (int ki = 0; ki < nk; ki++) {
        if (ki + 1 < nk) { issue((ki + 1) << 5, (ki + 1) & 1); CP_WAIT(1); }
        else { CP_WAIT(0); }
        __syncthreads();
        uint32_t sA = sA0 + (ki & 1) * (STG_WORDS * 4);
        uint32_t sB = sB0 + (ki & 1) * (STG_WORDS * 4);
#pragma unroll
        for (int ks = 0; ks < 4; ks++) {
            int kk = ks * 8;
            uint32_t af[2][4], bf[8][2];
#pragma unroll
            for (int mi = 0; mi < 2; mi++)
                ldsm4(af[mi], sA + ((wm + mi * 16 + a_r) * PAD + kk + a_c) * 4);
#pragma unroll
            for (int p = 0; p < 4; p++) {
                uint32_t t[4];
                ldsm4(t, sB + ((wn + p * 16 + b_r) * PAD + kk + b_c) * 4);
                bf[2 * p][0] = t[0]; bf[2 * p][1] = t[1];
                bf[2 * p + 1][0] = t[2]; bf[2 * p + 1][1] = t[3];
            }
#pragma unroll
            for (int mi = 0; mi < 2; mi++)
#pragma unroll
                for (int ni = 0; ni < 8; ni++) mma8(acc[mi][ni], af[mi], bf[ni]);
        }
        __syncthreads();
    }
#pragma unroll
    for (int mi = 0; mi < 2; mi++) {
        int r0 = bm + wm + mi * 16 + lq;
#pragma unroll
        for (int ni = 0; ni < 8; ni++) {
            int col = bn + wn + ni * 8 + 2 * lr;
#pragma unroll
            for (int rr = 0; rr < 2; rr++) {
                int m = r0 + rr * 8;
                float v0 = acc[mi][ni][rr * 2 + 0];
                float v1 = acc[mi][ni][rr * 2 + 1];
                if (EPI == 1) { v0 = fmaxf(v0 + bias[col], 0.f); v1 = fmaxf(v1 + bias[col + 1], 0.f); }
                if (EPI == 2) {
                    v0 += bias[col] + res[(size_t)m * ldres + col];
                    v1 += bias[col + 1] + res[(size_t)m * ldres + col + 1];
                }
                if (EPI == 3) {
                    v0 += res[(size_t)m * ldres + col];
                    v1 += res[(size_t)m * ldres + col + 1];
                }
                if (RND) { v0 = tf32r(v0); v1 = tf32r(v1); }
                *(float2*)(C + (size_t)m * ldc + col) = make_float2(v0, v1);
            }
        }
    }
}

// ---------------------------------------------------------------------------
// Scores: e = exp((Q K^T)/8 * prior, masked) -> attn region, partial rowsums.
// q,k are column slices of merged qkv (lda = QLD). ldmatrix fragments.
// ---------------------------------------------------------------------------
__global__ void __launch_bounds__(256, 2) scores_tc(
    const float* __restrict__ qkv,
    const float* __restrict__ prior, const int* __restrict__ mask,
    float* __restrict__ attn, float* __restrict__ rpart) {
    int z = blockIdx.z;
    int b = z >> 4, h = z & 15;
    const float* A = qkv + (size_t)b * LL * QLD + h * DKK;            // Q
    const float* B = qkv + (size_t)b * LL * QLD + DD + h * DKK;       // K
    float* Cp = attn + (size_t)z * LL * LL;
    int bm = blockIdx.y * 128, bn = blockIdx.x * 128;
    __shared__ uint32_t As[128 * PAD];
    __shared__ uint32_t Bs[128 * PAD];
    __shared__ float rsh[128][2];
    int tid = threadIdx.x, lane = tid & 31, warp = tid >> 5;
    int wm = (warp & 3) * 32, wn2 = warp >> 2;
    int wn = wn2 * 64;
    int lq = lane >> 2, lr = lane & 3;
    int a_r = lane & 15, a_c = (lane >> 4) << 2;
    int b_r = (lane & 7) + ((lane & 16) ? 8 : 0);
    int b_c = (lane & 8) ? 4 : 0;
    uint32_t sA0 = (uint32_t)__cvta_generic_to_shared(As);
    uint32_t sB0 = (uint32_t)__cvta_generic_to_shared(Bs);
    float acc[2][8][4];
#pragma unroll
    for (int mi = 0; mi < 2; mi++)
#pragma unroll
        for (int ni = 0; ni < 8; ni++)
#pragma unroll
            for (int j = 0; j < 4; j++) acc[mi][ni][j] = 0.f;

    for (int k0 = 0; k0 < DKK; k0 += 32) {
#pragma unroll
        for (int i = 0; i < 4; i++) {
            int idx = tid + i * 256;
            int row = idx >> 3, c4 = (idx & 7) << 2;
            uint4 va = *(const uint4*)(A + (size_t)(bm + row) * QLD + k0 + c4);
            *(uint4*)&As[row * PAD + c4] = va;
            uint4 vb = *(const uint4*)(B + (size_t)(bn + row) * QLD + k0 + c4);
            *(uint4*)&Bs[row * PAD + c4] = vb;
        }
        __syncthreads();
#pragma unroll
        for (int ks = 0; ks < 4; ks++) {
            int kk = ks * 8;
            uint32_t af[2][4], bf[8][2];
#pragma unroll
            for (int mi = 0; mi < 2; mi++)
                ldsm4(af[mi], sA0 + ((wm + mi * 16 + a_r) * PAD + kk + a_c) * 4);
#pragma unroll
            for (int p = 0; p < 4; p++) {
                uint32_t t[4];
                ldsm4(t, sB0 + ((wn + p * 16 + b_r) * PAD + kk + b_c) * 4);
                bf[2 * p][0] = t[0]; bf[2 * p][1] = t[1];
                bf[2 * p + 1][0] = t[2]; bf[2 * p + 1][1] = t[3];
            }
#pragma unroll
            for (int mi = 0; mi < 2; mi++)
#pragma unroll
                for (int ni = 0; ni < 8; ni++) mma8(acc[mi][ni], af[mi], bf[ni]);
        }
        __syncthreads();
    }
#pragma unroll
    for (int mi = 0; mi < 2; mi++) {
        int r0 = bm + wm + mi * 16 + lq;
        float rsum[2] = {0.f, 0.f};
#pragma unroll
        for (int ni = 0; ni < 8; ni++) {
            int col = bn + wn + ni * 8 + 2 * lr;
            int m0 = mask[b * LL + col], m1 = mask[b * LL + col + 1];
#pragma unroll
            for (int rr = 0; rr < 2; rr++) {
                int m = r0 + rr * 8;
                const float* prow = prior + ((size_t)b * LL + m) * LL + col;
                float v0 = acc[mi][ni][rr * 2 + 0] * 0.125f * prow[0];
                float v1 = acc[mi][ni][rr * 2 + 1] * 0.125f * prow[1];
                if (m0 == 0) v0 = -1e9f;
                if (m1 == 0) v1 = -1e9f;
                float e0 = expf(v0), e1 = expf(v1);
                rsum[rr] += e0 + e1;
                *(float2*)(Cp + (size_t)m * LL + col) = make_float2(e0, e1);
            }
        }
#pragma unroll
        for (int rr = 0; rr < 2; rr++) {
            float s = rsum[rr];
            s += __shfl_xor_sync(0xffffffffu, s, 1);
            s += __shfl_xor_sync(0xffffffffu, s, 2);
            if (lr == 0) rsh[wm + mi * 16 + lq + rr * 8][wn2] = s;
        }
    }
    __syncthreads();
    if (tid < 128)
        rpart[((size_t)z * LL + bm + tid) * 16 + blockIdx.x] = rsh[tid][0] + rsh[tid][1];
}

// ---------------------------------------------------------------------------
// AV fused normalize: reads e, writes p = e*inv to attn, O = (e @ V)*inv.
// cp.async 2-stage; A-frags via ldmatrix + cvt; V frags scalar (k-major).
// ---------------------------------------------------------------------------
__global__ void __launch_bounds__(256, 2) av_tc(float* __restrict__ attn,
                                                const float* __restrict__ qkv,
                                                const float* __restrict__ rpart,
                                                float* __restrict__ o) {
    extern __shared__ uint32_t sh[];
    uint32_t* AsBase = sh;
    uint32_t* BsBase = sh + 2 * STG_WORDS;
    float* invl = (float*)(sh + 2 * STG_WORDS + 2 * 32 * VPAD);
    int z = blockIdx.z;
    int b = z >> 4, h = z & 15;
    float* A = attn + (size_t)z * LL * LL;
    const float* Vp = qkv + (size_t)b * LL * QLD + 2 * DD + h * DKK;
    float* Cp = o + (size_t)b * LL * DD + h * DKK;
    int bm = blockIdx.y * 128;
    int tid = threadIdx.x, lane = tid & 31, warp = tid >> 5;
    int wm = warp * 16;
    int lq = lane >> 2, lr = lane & 3;
    int a_r = lane & 15, a_c = (lane >> 4) << 2;
    uint32_t sA0 = (uint32_t)__cvta_generic_to_shared(AsBase);

    if (tid < 128) {
        const float* rp = rpart + ((size_t)z * LL + bm + tid) * 16;
        float s = 0.f;
#pragma unroll
        for (int i = 0; i < 16; i++) s += rp[i];
        invl[tid] = 1.f / s;
    }

    auto issue = [&](int k0, int buf) {
        uint32_t* Asb = AsBase + buf * STG_WORDS;
        uint32_t* Bsb = BsBase + buf * (32 * VPAD);
#pragma unroll
        for (int i = 0; i < 4; i++) {
            int idx = tid + i * 256;
            int row = idx >> 3, c4 = (idx & 7) << 2;
            const float* ga = A + (size_t)(bm + row) * LL + k0 + c4;
            uint32_t sa = (uint32_t)__cvta_generic_to_shared(&Asb[row * PAD + c4]);
            CP16(sa, ga);
        }
#pragma unroll
        for (int i = 0; i < 2; i++) {
            int idx = tid + i * 256;
            int krow = idx >> 4, c4 = (idx & 15) << 2;
            const float* gb = Vp + (size_t)(k0 + krow) * QLD + c4;
            uint32_t sb = (uint32_t)__cvta_generic_to_shared(&Bsb[krow * VPAD + c4]);
            CP16(sb, gb);
        }
        CP_COMMIT();
    };

    float acc[8][4];
#pragma unroll
    for (int ni = 0; ni < 8; ni++)
#pragma unroll
        for (int j = 0; j < 4; j++) acc[ni][j] = 0.f;

    const int nk = LL / 32;
    issue(0, 0);
    for (int ki = 0; ki < nk; ki++) {
        if (ki + 1 < nk) { issue((ki + 1) << 5, (ki + 1) & 1); CP_WAIT(1); }
        else { CP_WAIT(0); }
        __syncthreads();
        const uint32_t* As = AsBase + (ki & 1) * STG_WORDS;
        const uint32_t* Bs = BsBase + (ki & 1) * (32 * VPAD);
        uint32_t sA = sA0 + (ki & 1) * (STG_WORDS * 4);
        int k0 = ki << 5;
        // write normalized p back to attn (overlaps MMA)
#pragma unroll
        for (int i = 0; i < 4; i++) {
            int idx = tid + i * 256;
            int row = idx >> 3, c4 = (idx & 7) << 2;
            float4 e = *(const float4*)&As[row * PAD + c4];
            float il = invl[row];
            e.x *= il; e.y *= il; e.z *= il; e.w *= il;
            *(float4*)(A + (size_t)(bm + row) * LL + k0 + c4) = e;
        }
#pragma unroll
        for (int ks = 0; ks < 4; ks++) {
            int kk = ks * 8;
            uint32_t af[4], bf[8][2];
            ldsm4(af, sA + ((wm + a_r) * PAD + kk + a_c) * 4);
            af[0] = f2t(__uint_as_float(af[0]));
            af[1] = f2t(__uint_as_float(af[1]));
            af[2] = f2t(__uint_as_float(af[2]));
            af[3] = f2t(__uint_as_float(af[3]));
#pragma unroll
            for (int ni = 0; ni < 8; ni++) {
                int n = ni * 8 + lq;
                bf[ni][0] = Bs[(kk + lr) * VPAD + n];
                bf[ni][1] = Bs[(kk + lr + 4) * VPAD + n];
            }
#pragma unroll
            for (int ni = 0; ni < 8; ni++) mma8(acc[ni], af, bf[ni]);
        }
        __syncthreads();
    }
    int mloc = wm + lq;
#pragma unroll
    for (int ni = 0; ni < 8; ni++) {
        int col = ni * 8 + 2 * lr;
#pragma unroll
        for (int rr = 0; rr < 2; rr++) {
            int m = bm + mloc + rr * 8;
            float il = invl[mloc + rr * 8];
            *(float2*)(Cp + (size_t)m * DD + col) =
                make_float2(tf32r(acc[ni][rr * 2 + 0] * il), tf32r(acc[ni][rr * 2 + 1] * il));
        }
    }
}

// ---------------------------------------------------------------------------
// Launch
// ---------------------------------------------------------------------------
extern "C" void kernel_launch(void* const* d_in, const int* in_sizes, int n_in,
                              void* d_out, int out_size) {
    const float* src    = (const float*)d_in[0];
    const int*   mask   = (const int*)d_in[1];
    const float* prior  = (const float*)d_in[2];
    const float* ln1_g  = (const float*)d_in[3];
    const float* ln1_b  = (const float*)d_in[4];
    const float* wq     = (const float*)d_in[5];
    const float* wk     = (const float*)d_in[6];
    const float* wv     = (const float*)d_in[7];
    const float* fc_w   = (const float*)d_in[8];
    const float* ln2_g  = (const float*)d_in[9];
    const float* ln2_b  = (const float*)d_in[10];
    const float* w1_w   = (const float*)d_in[11];
    const float* w1_b   = (const float*)d_in[12];
    const float* w2_w   = (const float*)d_in[13];
    const float* w2_b   = (const float*)d_in[14];

    float* out = (float*)d_out;
    float* y_out = out;
    float* attn_out = out + ATTN_OFF;

    float *x, *qkv, *o, *y1, *zz, *hh, *rp;
    float *wqkvt, *fct, *w1t, *w2t;
    cudaGetSymbolAddress((void**)&x,   g_x);
    cudaGetSymbolAddress((void**)&qkv, g_qkv);
    cudaGetSymbolAddress((void**)&o,   g_o);
    cudaGetSymbolAddress((void**)&y1,  g_y1);
    cudaGetSymbolAddress((void**)&zz,  g_z);
    cudaGetSymbolAddress((void**)&hh,  g_h);
    cudaGetSymbolAddress((void**)&rp,  g_rpart);
    cudaGetSymbolAddress((void**)&wqkvt, g_wqkvt);
    cudaGetSymbolAddress((void**)&fct, g_fct);
    cudaGetSymbolAddress((void**)&w1t, g_w1t);
    cudaGetSymbolAddress((void**)&w2t, g_w2t);

    const int GSMEM = 4 * 4 * STG_WORDS;                           // 73728 B
    const int AVSMEM = 4 * (2 * STG_WORDS + 2 * 32 * VPAD) + 512;  // ~91648 B
    static bool attr_set = false;
    if (!attr_set) {
        cudaFuncSetAttribute((const void*)gemm_tc<0, true>,  cudaFuncAttributeMaxDynamicSharedMemorySize, GSMEM);
        cudaFuncSetAttribute((const void*)gemm_tc<1, true>,  cudaFuncAttributeMaxDynamicSharedMemorySize, GSMEM);
        cudaFuncSetAttribute((const void*)gemm_tc<2, false>, cudaFuncAttributeMaxDynamicSharedMemorySize, GSMEM);
        cudaFuncSetAttribute((const void*)gemm_tc<3, false>, cudaFuncAttributeMaxDynamicSharedMemorySize, GSMEM);
        cudaFuncSetAttribute((const void*)av_tc, cudaFuncAttributeMaxDynamicSharedMemorySize, AVSMEM);
        attr_set = true;
    }

    // Pre-round weights to tf32; wq/wk/wv concatenated into one [3072,1024]
    const int NW1 = DD * DD / 4;
    const int NW2 = DFF * DD / 4;
    cvt_kernel<<<(NW1 + 255) / 256, 256>>>(wq, wqkvt, NW1);
    cvt_kernel<<<(NW1 + 255) / 256, 256>>>(wk, wqkvt + (size_t)DD * DD, NW1);
    cvt_kernel<<<(NW1 + 255) / 256, 256>>>(wv, wqkvt + (size_t)2 * DD * DD, NW1);
    cvt_kernel<<<(NW1 + 255) / 256, 256>>>(fc_w, fct, NW1);
    cvt_kernel<<<(NW2 + 255) / 256, 256>>>(w1_w, w1t, NW2);
    cvt_kernel<<<(NW2 + 255) / 256, 256>>>(w2_w, w2t, NW2);

    ln_kernel<<<MROWS, 256>>>(src, ln1_g, ln1_b, x);

    // merged QKV projection: [8192,1024] @ [3072,1024]^T -> [8192,3072]
    gemm_tc<0, true><<<dim3(QLD / 128, MROWS / 128), 256, GSMEM>>>(
        x, DD, wqkvt, DD, qkv, QLD, DD, nullptr, nullptr, 0);

    scores_tc<<<dim3(LL / 128, LL / 128, BB * HH), 256>>>(qkv, prior, mask, attn_out, rp);

    av_tc<<<dim3(1, LL / 128, BB * HH), 256, AVSMEM>>>(attn_out, qkv, rp, o);

    dim3 gproj(DD / 128, MROWS / 128);
    gemm_tc<3, false><<<gproj, 256, GSMEM>>>(o, DD, fct, DD, y1, DD, DD, nullptr, src, DD);

    ln_kernel<<<MROWS, 256>>>(y1, ln2_g, ln2_b, zz);

    gemm_tc<1, true><<<dim3(DFF / 128, MROWS / 128), 256, GSMEM>>>(zz, DD, w1t, DD, hh, DFF, DD, w1_b, nullptr, 0);

    gemm_tc<2, false><<<gproj, 256, GSMEM>>>(hh, DFF, w2t, DFF, y_out, DD, DFF, w2_b, y1, DD);
}